// round 6
// baseline (speedup 1.0000x reference)
#include <cuda_runtime.h>
#include <cuda_bf16.h>
#include <cstdint>

#define B_ 8
#define N_ 1024
#define C_ 64

// ---------------- device scratch (allocation-free rule) ----------------
__device__ __nv_bfloat16 g_LH[B_ * N_ * N_];
__device__ __nv_bfloat16 g_LL[B_ * N_ * N_];
__device__ __nv_bfloat16 g_xH[B_ * N_ * C_];
__device__ __nv_bfloat16 g_xL[B_ * N_ * C_];
__device__ __nv_bfloat16 g_z1H[B_ * N_ * C_];
__device__ __nv_bfloat16 g_z1L[B_ * N_ * C_];
__device__ __nv_bfloat16 g_z2H[B_ * N_ * C_];
__device__ __nv_bfloat16 g_z2L[B_ * N_ * C_];
__device__ float         g_Z1f[B_ * N_ * C_];
__device__ __nv_bfloat16 g_thH[4 * 64 * 64];
__device__ __nv_bfloat16 g_thL[4 * 64 * 64];

// ---------------- helpers ----------------
__device__ __forceinline__ uint32_t smem_u32(const void* p) {
    uint32_t a;
    asm("{ .reg .u64 t; cvta.to.shared.u64 t, %1; cvt.u32.u64 %0, t; }" : "=r"(a) : "l"(p));
    return a;
}
__device__ __forceinline__ void cp16(uint32_t d, const void* s) {
    asm volatile("cp.async.cg.shared.global [%0], [%1], 16;" :: "r"(d), "l"(s));
}
#define CP_COMMIT() asm volatile("cp.async.commit_group;" ::: "memory")

__device__ __forceinline__ void split2(float a, float b, uint32_t& hi, uint32_t& lo) {
    __nv_bfloat16 ha = __float2bfloat16(a), hb = __float2bfloat16(b);
    hi = (uint32_t)__bfloat16_as_ushort(ha) | ((uint32_t)__bfloat16_as_ushort(hb) << 16);
    __nv_bfloat16 la = __float2bfloat16(a - __bfloat162float(ha));
    __nv_bfloat16 lb = __float2bfloat16(b - __bfloat162float(hb));
    lo = (uint32_t)__bfloat16_as_ushort(la) | ((uint32_t)__bfloat16_as_ushort(lb) << 16);
}

#define LDSM4(R, A) asm volatile( \
    "ldmatrix.sync.aligned.m8n8.x4.shared.b16 {%0,%1,%2,%3}, [%4];" \
    : "=r"((R)[0]), "=r"((R)[1]), "=r"((R)[2]), "=r"((R)[3]) : "r"(A))
#define LDSM4T(R, A) asm volatile( \
    "ldmatrix.sync.aligned.m8n8.x4.trans.shared.b16 {%0,%1,%2,%3}, [%4];" \
    : "=r"((R)[0]), "=r"((R)[1]), "=r"((R)[2]), "=r"((R)[3]) : "r"(A))
#define MMA16816(D, A, B0, B1) asm volatile( \
    "mma.sync.aligned.m16n8k16.row.col.f32.bf16.bf16.f32 " \
    "{%0,%1,%2,%3},{%4,%5,%6,%7},{%8,%9},{%0,%1,%2,%3};" \
    : "+f"((D)[0]), "+f"((D)[1]), "+f"((D)[2]), "+f"((D)[3]) \
    : "r"((A)[0]), "r"((A)[1]), "r"((A)[2]), "r"((A)[3]), "r"(B0), "r"(B1))

// 64x(32 n-cols per warp) bf16-split MMA block over kk in [kk0,kk1) (kk = 16-k slice).
__device__ __forceinline__ void mma_block64(
    uint32_t aH, uint32_t aL, uint32_t bH, uint32_t bL,
    int wm, int wn, int lane, int kk0, int kk1, float acc[4][4]) {
    const int tile = lane >> 3, tl = lane & 7;
    const int arow = wm * 16 + ((tile & 1) << 3) + tl;
    const uint32_t arb = (uint32_t)arow * 128;
    const int arx = arow & 7;
    const int aks0 = tile >> 1;
    const int krl = ((tile & 1) << 3) + tl;
    const int bs0 = wn * 4 + (tile >> 1);
    #pragma unroll
    for (int kk = kk0; kk < kk1; kk++) {
        uint32_t aso = arb + (uint32_t)(((aks0 + kk * 2) ^ arx) << 4);
        uint32_t AH4[4], AL4[4];
        LDSM4(AH4, aH + aso);
        LDSM4(AL4, aL + aso);
        const int kr = kk * 16 + krl;
        const int krx = kr & 7;
        const uint32_t krb = (uint32_t)kr * 128;
        uint32_t bso0 = krb + (uint32_t)(((bs0 + 0) ^ krx) << 4);
        uint32_t bso1 = krb + (uint32_t)(((bs0 + 2) ^ krx) << 4);
        uint32_t BH0[4], BH1[4], BL0[4], BL1[4];
        LDSM4T(BH0, bH + bso0);
        LDSM4T(BH1, bH + bso1);
        LDSM4T(BL0, bL + bso0);
        LDSM4T(BL1, bL + bso1);
        MMA16816(acc[0], AH4, BH0[0], BH0[1]);
        MMA16816(acc[1], AH4, BH0[2], BH0[3]);
        MMA16816(acc[2], AH4, BH1[0], BH1[1]);
        MMA16816(acc[3], AH4, BH1[2], BH1[3]);
        MMA16816(acc[0], AH4, BL0[0], BL0[1]);
        MMA16816(acc[1], AH4, BL0[2], BL0[3]);
        MMA16816(acc[2], AH4, BL1[0], BL1[1]);
        MMA16816(acc[3], AH4, BL1[2], BL1[3]);
        MMA16816(acc[0], AL4, BH0[0], BH0[1]);
        MMA16816(acc[1], AL4, BH0[2], BH0[3]);
        MMA16816(acc[2], AL4, BH1[0], BH1[1]);
        MMA16816(acc[3], AL4, BH1[2], BH1[3]);
    }
}

// ---------------- prep: fp32 -> bf16 hi/lo split (x, theta only) ----------------
__global__ __launch_bounds__(256) void split_k(const float4* __restrict__ s,
                                               uint2* __restrict__ h,
                                               uint2* __restrict__ l, int n4) {
    for (int i = blockIdx.x * blockDim.x + threadIdx.x; i < n4; i += gridDim.x * blockDim.x) {
        float4 v = s[i];
        uint32_t h0, l0, h1, l1;
        split2(v.x, v.y, h0, l0);
        split2(v.z, v.w, h1, l1);
        h[i] = make_uint2(h0, h1);
        l[i] = make_uint2(l0, l1);
    }
}

// ---------------- main pass kernel ----------------
// stage (32KB): A hi [0,8K) + A lo [8K,16K)  (PASS 1: fp32 A [0,16K) pre-convert)
//               B hi [16K,24K), B lo [24K,32K)
#define STG    32768
#define O_ACC  (4 * STG)           // 16KB fp32 accumulator exchange
#define O_ZH   (O_ACC + 16384)
#define O_ZL   (O_ZH + 8192)
#define O_TH   (O_ZL + 8192)
#define O_TL   (O_TH + 8192)
#define O_XH   (O_TL + 8192)
#define O_XL   (O_XH + 8192)
#define O_T0H  (O_XL + 8192)
#define O_T0L  (O_T0H + 8192)
#define SMEMSZ (O_T0L + 8192)      // 212992 bytes

template <int PASS>
__global__ void __launch_bounds__(512, 1) cheb(
    const float* __restrict__ Lf,                                        // PASS 1 only
    const __nv_bfloat16* __restrict__ LH, const __nv_bfloat16* __restrict__ LL,  // PASS 2/3
    const __nv_bfloat16* __restrict__ BHg, const __nv_bfloat16* __restrict__ BLg,
    const float* __restrict__ Sub,
    const __nv_bfloat16* __restrict__ thH, const __nv_bfloat16* __restrict__ thL,
    const __nv_bfloat16* __restrict__ xH, const __nv_bfloat16* __restrict__ xL,
    float* __restrict__ Zf,
    __nv_bfloat16* __restrict__ ZoH, __nv_bfloat16* __restrict__ ZoL,
    __nv_bfloat16* __restrict__ LHo, __nv_bfloat16* __restrict__ LLo,    // PASS 1 writes
    float* __restrict__ out) {

    extern __shared__ char smem[];
    const uint32_t sb = smem_u32(smem);
    const int tid = threadIdx.x, lane = tid & 31, wid = tid >> 5;
    const int wg = wid >> 3, w8 = wid & 7;
    const int wm = w8 & 3, wn = w8 >> 2;
    const int b = blockIdx.y, m0 = blockIdx.x * 64;

    auto load_chunk = [&](int k0, int s) {
        const uint32_t st = sb + (uint32_t)s * STG;
        if (PASS == 1) {
            #pragma unroll
            for (int i = 0; i < 2; i++) {
                const int idx = tid + i * 512;
                const int row = idx >> 4, sg = idx & 15;
                cp16(st + (uint32_t)row * 256 + sg * 16,
                     Lf + ((size_t)(b * N_ + m0 + row)) * N_ + k0 + sg * 4);
            }
        } else {
            const int row = tid >> 3, seg = tid & 7;
            const uint32_t so = (uint32_t)row * 128 + (uint32_t)((seg ^ (row & 7)) << 4);
            cp16(st + so,        LH + ((size_t)(b * N_ + m0 + row)) * N_ + k0 + seg * 8);
            cp16(st + 8192 + so, LL + ((size_t)(b * N_ + m0 + row)) * N_ + k0 + seg * 8);
        }
        {
            const int row = tid >> 3, seg = tid & 7;
            const uint32_t so = (uint32_t)row * 128 + (uint32_t)((seg ^ (row & 7)) << 4);
            cp16(st + 16384 + so, BHg + (size_t)(b * N_ + k0 + row) * C_ + seg * 8);
            cp16(st + 24576 + so, BLg + (size_t)(b * N_ + k0 + row) * C_ + seg * 8);
        }
        CP_COMMIT();
    };

    float acc[4][4] = {};
    load_chunk(0, 0);
    load_chunk(64, 1);
    load_chunk(128, 2);

    for (int ch = 0; ch < 16; ch++) {
        if (ch < 14)       asm volatile("cp.async.wait_group 2;" ::: "memory");
        else if (ch == 14) asm volatile("cp.async.wait_group 1;" ::: "memory");
        else               asm volatile("cp.async.wait_group 0;" ::: "memory");
        __syncthreads();
        const int s = ch & 3;
        const uint32_t st = sb + (uint32_t)s * STG;
        char* stp = smem + (size_t)s * STG;

        if (PASS == 1) {
            // convert fp32 A chunk -> bf16 hi/lo in-place; also persist to global
            const int r = tid >> 3, cs = tid & 7;
            float4 f0 = *(const float4*)(stp + r * 256 + cs * 32);
            float4 f1 = *(const float4*)(stp + r * 256 + cs * 32 + 16);
            __syncthreads();
            uint4 hv, lv;
            split2(f0.x, f0.y, hv.x, lv.x);
            split2(f0.z, f0.w, hv.y, lv.y);
            split2(f1.x, f1.y, hv.z, lv.z);
            split2(f1.z, f1.w, hv.w, lv.w);
            const uint32_t so = (uint32_t)r * 128 + (uint32_t)((cs ^ (r & 7)) << 4);
            *(uint4*)(stp + so) = hv;
            *(uint4*)(stp + 8192 + so) = lv;
            const size_t go = ((size_t)(b * N_ + m0 + r)) * N_ + ch * 64 + cs * 8;
            *(uint4*)(LHo + go) = hv;
            *(uint4*)(LLo + go) = lv;
            __syncthreads();
        }

        mma_block64(st, st + 8192, st + 16384, st + 24576,
                    wm, wn, lane, wg * 2, wg * 2 + 2, acc);

        if (ch + 3 < 16) load_chunk((ch + 3) * 64, (ch + 3) & 3);
    }
    __syncthreads();

    const int crow = wm * 16 + (lane >> 2);
    const int ccol = wn * 32 + 2 * (lane & 3);
    float* ACCp = (float*)(smem + O_ACC);

    // group1 publishes its partial accumulators
    if (wg == 1) {
        #pragma unroll
        for (int j = 0; j < 4; j++)
            #pragma unroll
            for (int h = 0; h < 2; h++) {
                ACCp[(crow + 8 * h) * 64 + ccol + j * 8]     = acc[j][2 * h];
                ACCp[(crow + 8 * h) * 64 + ccol + j * 8 + 1] = acc[j][2 * h + 1];
            }
    }
    __syncthreads();

    if (wg == 0) {
        // reduce + zn = alpha*acc - Sub
        float zn[4][4];
        #pragma unroll
        for (int j = 0; j < 4; j++)
            #pragma unroll
            for (int h = 0; h < 2; h++) {
                float a0 = acc[j][2 * h]     + ACCp[(crow + 8 * h) * 64 + ccol + j * 8];
                float a1 = acc[j][2 * h + 1] + ACCp[(crow + 8 * h) * 64 + ccol + j * 8 + 1];
                zn[j][2 * h] = a0;
                zn[j][2 * h + 1] = a1;
            }
        if (PASS > 1) {
            const float* Sb = Sub + ((size_t)(b * N_ + m0)) * C_;
            #pragma unroll
            for (int j = 0; j < 4; j++) {
                float2 s0 = *(const float2*)(Sb + (size_t)crow * C_ + ccol + j * 8);
                float2 s1 = *(const float2*)(Sb + (size_t)(crow + 8) * C_ + ccol + j * 8);
                zn[j][0] = 2.f * zn[j][0] - s0.x;
                zn[j][1] = 2.f * zn[j][1] - s0.y;
                zn[j][2] = 2.f * zn[j][2] - s1.x;
                zn[j][3] = 2.f * zn[j][3] - s1.y;
            }
        }
        // zn -> smem bf16 hi/lo (SW128 rows)
        #pragma unroll
        for (int j = 0; j < 4; j++) {
            const int seg = wn * 4 + j;
            const int off = (lane & 3) * 4;
            #pragma unroll
            for (int h = 0; h < 2; h++) {
                const int row = crow + h * 8;
                uint32_t hi, lo;
                split2(zn[j][2 * h], zn[j][2 * h + 1], hi, lo);
                const uint32_t so = (uint32_t)row * 128 + (uint32_t)((seg ^ (row & 7)) << 4) + off;
                *(uint32_t*)(smem + O_ZH + so) = hi;
                *(uint32_t*)(smem + O_ZL + so) = lo;
            }
        }
        if (PASS == 1) {  // z1 fp32 for pass3's Sub
            float* Zb = Zf + ((size_t)(b * N_ + m0)) * C_;
            #pragma unroll
            for (int j = 0; j < 4; j++) {
                *(float2*)(Zb + (size_t)crow * C_ + ccol + j * 8)       = make_float2(zn[j][0], zn[j][1]);
                *(float2*)(Zb + (size_t)(crow + 8) * C_ + ccol + j * 8) = make_float2(zn[j][2], zn[j][3]);
            }
        }
    } else {
        // group1 stages theta (and x, theta0 for PASS 1)
        const __nv_bfloat16* tHk = thH + PASS * 4096;
        const __nv_bfloat16* tLk = thL + PASS * 4096;
        const int t2 = tid - 256;
        #pragma unroll
        for (int i = 0; i < 2; i++) {
            const int idx = t2 + i * 256;
            const int row = idx >> 3, seg = idx & 7;
            const uint32_t so = (uint32_t)row * 128 + (uint32_t)((seg ^ (row & 7)) << 4);
            *(uint4*)(smem + O_TH + so) = *(const uint4*)(tHk + row * 64 + seg * 8);
            *(uint4*)(smem + O_TL + so) = *(const uint4*)(tLk + row * 64 + seg * 8);
            if (PASS == 1) {
                *(uint4*)(smem + O_XH + so) = *(const uint4*)(xH + ((size_t)(b * N_ + m0 + row)) * C_ + seg * 8);
                *(uint4*)(smem + O_XL + so) = *(const uint4*)(xL + ((size_t)(b * N_ + m0 + row)) * C_ + seg * 8);
                *(uint4*)(smem + O_T0H + so) = *(const uint4*)(thH + row * 64 + seg * 8);
                *(uint4*)(smem + O_T0L + so) = *(const uint4*)(thL + row * 64 + seg * 8);
            }
        }
    }
    __syncthreads();

    if (wg == 0) {
        // theta epilogue on tensor cores
        float o[4][4] = {};
        mma_block64(sb + O_ZH, sb + O_ZL, sb + O_TH, sb + O_TL, wm, wn, lane, 0, 4, o);
        if (PASS == 1)
            mma_block64(sb + O_XH, sb + O_XL, sb + O_T0H, sb + O_T0L, wm, wn, lane, 0, 4, o);

        float* ob = out + ((size_t)(b * N_ + m0)) * C_;
        #pragma unroll
        for (int j = 0; j < 4; j++) {
            float2 v0 = make_float2(o[j][0], o[j][1]);
            float2 v1 = make_float2(o[j][2], o[j][3]);
            float* p0 = ob + (size_t)crow * C_ + ccol + j * 8;
            float* p1 = ob + (size_t)(crow + 8) * C_ + ccol + j * 8;
            if (PASS > 1) {
                float2 c0 = *(const float2*)p0, c1 = *(const float2*)p1;
                v0.x += c0.x; v0.y += c0.y; v1.x += c1.x; v1.y += c1.y;
            }
            *(float2*)p0 = v0;
            *(float2*)p1 = v1;
        }
    } else if (PASS < 3) {
        // group1: zn hi/lo -> global row-major [N][C] (next pass's B operand)
        const int t2 = tid - 256;
        #pragma unroll
        for (int i = 0; i < 2; i++) {
            const int idx = t2 + i * 256;
            const int row = idx >> 3, seg = idx & 7;
            const uint32_t so = (uint32_t)row * 128 + (uint32_t)((seg ^ (row & 7)) << 4);
            *(uint4*)(ZoH + ((size_t)(b * N_ + m0 + row)) * C_ + seg * 8) = *(const uint4*)(smem + O_ZH + so);
            *(uint4*)(ZoL + ((size_t)(b * N_ + m0 + row)) * C_ + seg * 8) = *(const uint4*)(smem + O_ZL + so);
        }
    }
}

extern "C" void kernel_launch(void* const* d_in, const int* in_sizes, int n_in,
                              void* d_out, int out_size) {
    (void)in_sizes; (void)n_in; (void)out_size;
    const float* x  = (const float*)d_in[0];   // [8,1024,64]
    const float* L  = (const float*)d_in[1];   // [8,1024,1024]
    const float* th = (const float*)d_in[2];   // [4,64,64]
    float* out = (float*)d_out;                // [8,1024,64]

    __nv_bfloat16 *lh, *ll, *xh, *xl, *z1h, *z1l, *z2h, *z2l, *thh, *thl;
    float* z1f;
    cudaGetSymbolAddress((void**)&lh, g_LH);
    cudaGetSymbolAddress((void**)&ll, g_LL);
    cudaGetSymbolAddress((void**)&xh, g_xH);
    cudaGetSymbolAddress((void**)&xl, g_xL);
    cudaGetSymbolAddress((void**)&z1h, g_z1H);
    cudaGetSymbolAddress((void**)&z1l, g_z1L);
    cudaGetSymbolAddress((void**)&z2h, g_z2H);
    cudaGetSymbolAddress((void**)&z2l, g_z2L);
    cudaGetSymbolAddress((void**)&thh, g_thH);
    cudaGetSymbolAddress((void**)&thl, g_thL);
    cudaGetSymbolAddress((void**)&z1f, g_Z1f);

    static bool attr_done = false;
    if (!attr_done) {
        cudaFuncSetAttribute(cheb<1>, cudaFuncAttributeMaxDynamicSharedMemorySize, SMEMSZ);
        cudaFuncSetAttribute(cheb<2>, cudaFuncAttributeMaxDynamicSharedMemorySize, SMEMSZ);
        cudaFuncSetAttribute(cheb<3>, cudaFuncAttributeMaxDynamicSharedMemorySize, SMEMSZ);
        attr_done = true;
    }

    // small preps: x and theta hi/lo splits (L split is fused into pass 1)
    split_k<<<512, 256>>>((const float4*)x, (uint2*)xh, (uint2*)xl, B_ * N_ * C_ / 4);
    split_k<<<16, 256>>>((const float4*)th, (uint2*)thh, (uint2*)thl, 4 * 64 * 64 / 4);

    dim3 grid(16, 8);
    // pass1: z1 = L x ; out  = x@th0 + z1@th1 ; side: z1f, z1 hi/lo, LH/LL
    cheb<1><<<grid, 512, SMEMSZ>>>(L, nullptr, nullptr, xh, xl, nullptr,
                                   thh, thl, xh, xl, z1f, z1h, z1l, lh, ll, out);
    // pass2: z2 = 2 L z1 - x ; out += z2@th2 ; side: z2 hi/lo
    cheb<2><<<grid, 512, SMEMSZ>>>(nullptr, lh, ll, z1h, z1l, x,
                                   thh, thl, xh, xl, nullptr, z2h, z2l, nullptr, nullptr, out);
    // pass3: z3 = 2 L z2 - z1 ; out += z3@th3
    cheb<3><<<grid, 512, SMEMSZ>>>(nullptr, lh, ll, z2h, z2l, z1f,
                                   thh, thl, xh, xl, nullptr, nullptr, nullptr, nullptr, nullptr, out);
}

// round 8
// speedup vs baseline: 1.0150x; 1.0150x over previous
#include <cuda_runtime.h>
#include <cuda_bf16.h>
#include <cstdint>

#define B_ 8
#define N_ 1024
#define C_ 64

// ---------------- device scratch (allocation-free rule) ----------------
__device__ __nv_bfloat16 g_LH[B_ * N_ * N_];
__device__ __nv_bfloat16 g_LL[B_ * N_ * N_];
__device__ __nv_bfloat16 g_xH[B_ * N_ * C_];
__device__ __nv_bfloat16 g_xL[B_ * N_ * C_];
__device__ __nv_bfloat16 g_z1H[B_ * N_ * C_];
__device__ __nv_bfloat16 g_z1L[B_ * N_ * C_];
__device__ __nv_bfloat16 g_z2H[B_ * N_ * C_];
__device__ __nv_bfloat16 g_z2L[B_ * N_ * C_];
__device__ float         g_Z1f[B_ * N_ * C_];
__device__ __nv_bfloat16 g_thH[4 * 64 * 64];
__device__ __nv_bfloat16 g_thL[4 * 64 * 64];

// ---------------- helpers ----------------
__device__ __forceinline__ uint32_t smem_u32(const void* p) {
    uint32_t a;
    asm("{ .reg .u64 t; cvta.to.shared.u64 t, %1; cvt.u32.u64 %0, t; }" : "=r"(a) : "l"(p));
    return a;
}
__device__ __forceinline__ void cp16(uint32_t d, const void* s) {
    asm volatile("cp.async.cg.shared.global [%0], [%1], 16;" :: "r"(d), "l"(s));
}
#define CP_COMMIT() asm volatile("cp.async.commit_group;" ::: "memory")

__device__ __forceinline__ void split2(float a, float b, uint32_t& hi, uint32_t& lo) {
    __nv_bfloat16 ha = __float2bfloat16(a), hb = __float2bfloat16(b);
    hi = (uint32_t)__bfloat16_as_ushort(ha) | ((uint32_t)__bfloat16_as_ushort(hb) << 16);
    __nv_bfloat16 la = __float2bfloat16(a - __bfloat162float(ha));
    __nv_bfloat16 lb = __float2bfloat16(b - __bfloat162float(hb));
    lo = (uint32_t)__bfloat16_as_ushort(la) | ((uint32_t)__bfloat16_as_ushort(lb) << 16);
}

#define LDSM4(R, A) asm volatile( \
    "ldmatrix.sync.aligned.m8n8.x4.shared.b16 {%0,%1,%2,%3}, [%4];" \
    : "=r"((R)[0]), "=r"((R)[1]), "=r"((R)[2]), "=r"((R)[3]) : "r"(A))
#define LDSM4T(R, A) asm volatile( \
    "ldmatrix.sync.aligned.m8n8.x4.trans.shared.b16 {%0,%1,%2,%3}, [%4];" \
    : "=r"((R)[0]), "=r"((R)[1]), "=r"((R)[2]), "=r"((R)[3]) : "r"(A))
#define MMA16816(D, A, B0, B1) asm volatile( \
    "mma.sync.aligned.m16n8k16.row.col.f32.bf16.bf16.f32 " \
    "{%0,%1,%2,%3},{%4,%5,%6,%7},{%8,%9},{%0,%1,%2,%3};" \
    : "+f"((D)[0]), "+f"((D)[1]), "+f"((D)[2]), "+f"((D)[3]) \
    : "r"((A)[0]), "r"((A)[1]), "r"((A)[2]), "r"((A)[3]), "r"(B0), "r"(B1))

// 16m x 32n per warp, bf16-split (hi*hi + hi*lo + lo*hi), kk in [kk0,kk1).
// A: smem rows(m) x 128B (64 bf16 k), SW128. B: smem rows(k) x 128B (64 bf16 n), SW128.
__device__ __forceinline__ void mma_block64(
    uint32_t aH, uint32_t aL, uint32_t bH, uint32_t bL,
    int wm, int wn, int lane, int kk0, int kk1, float acc[4][4]) {
    const int tile = lane >> 3, tl = lane & 7;
    const int arow = wm * 16 + ((tile & 1) << 3) + tl;
    const uint32_t arb = (uint32_t)arow * 128;
    const int arx = arow & 7;
    const int aks0 = tile >> 1;
    const int krl = ((tile & 1) << 3) + tl;
    const int bs0 = wn * 4 + (tile >> 1);
    #pragma unroll
    for (int kk = kk0; kk < kk1; kk++) {
        uint32_t aso = arb + (uint32_t)(((aks0 + kk * 2) ^ arx) << 4);
        uint32_t AH4[4], AL4[4];
        LDSM4(AH4, aH + aso);
        LDSM4(AL4, aL + aso);
        const int kr = kk * 16 + krl;
        const int krx = kr & 7;
        const uint32_t krb = (uint32_t)kr * 128;
        uint32_t bso0 = krb + (uint32_t)(((bs0 + 0) ^ krx) << 4);
        uint32_t bso1 = krb + (uint32_t)(((bs0 + 2) ^ krx) << 4);
        uint32_t BH0[4], BH1[4], BL0[4], BL1[4];
        LDSM4T(BH0, bH + bso0);
        LDSM4T(BH1, bH + bso1);
        LDSM4T(BL0, bL + bso0);
        LDSM4T(BL1, bL + bso1);
        MMA16816(acc[0], AH4, BH0[0], BH0[1]);
        MMA16816(acc[1], AH4, BH0[2], BH0[3]);
        MMA16816(acc[2], AH4, BH1[0], BH1[1]);
        MMA16816(acc[3], AH4, BH1[2], BH1[3]);
        MMA16816(acc[0], AH4, BL0[0], BL0[1]);
        MMA16816(acc[1], AH4, BL0[2], BL0[3]);
        MMA16816(acc[2], AH4, BL1[0], BL1[1]);
        MMA16816(acc[3], AH4, BL1[2], BL1[3]);
        MMA16816(acc[0], AL4, BH0[0], BH0[1]);
        MMA16816(acc[1], AL4, BH0[2], BH0[3]);
        MMA16816(acc[2], AL4, BH1[0], BH1[1]);
        MMA16816(acc[3], AL4, BH1[2], BH1[3]);
    }
}

// ---------------- prep: fp32 -> bf16 hi/lo split (x, theta only) ----------------
__global__ __launch_bounds__(256) void split_k(const float4* __restrict__ s,
                                               uint2* __restrict__ h,
                                               uint2* __restrict__ l, int n4) {
    for (int i = blockIdx.x * blockDim.x + threadIdx.x; i < n4; i += gridDim.x * blockDim.x) {
        float4 v = s[i];
        uint32_t h0, l0, h1, l1;
        split2(v.x, v.y, h0, l0);
        split2(v.z, v.w, h1, l1);
        h[i] = make_uint2(h0, h1);
        l[i] = make_uint2(l0, l1);
    }
}

// ---------------- main pass kernel ----------------
// M-tile = 32 rows, 256 threads (8 warps: wg{0,1} x wm{0,1} x wn{0,1}), 2 CTAs/SM.
// stage (24KB): A_hi [0,4K) A_lo [4K,8K) (PASS1: fp32 A [0,8K) pre-convert)
//               B_hi [8K,16K) B_lo [16K,24K)
#define STG_SZ 24576
// epilogue aliases (over stages 0/1/2 -- all consumed before reuse)
#define O_ACC  0
#define O_ZH   8192
#define O_ZL   12288
#define O_TH   16384
#define O_TL   24576
#define O_XH   32768
#define O_XL   36864
#define O_T0H  40960
#define O_T0L  49152
#define SMEMSZ (4 * STG_SZ)   // 98304

template <int PASS>
__global__ void __launch_bounds__(256, 2) cheb(
    const float* __restrict__ Lf,
    const __nv_bfloat16* __restrict__ LH, const __nv_bfloat16* __restrict__ LL,
    const __nv_bfloat16* __restrict__ BHg, const __nv_bfloat16* __restrict__ BLg,
    const float* __restrict__ Sub,
    const __nv_bfloat16* __restrict__ thH, const __nv_bfloat16* __restrict__ thL,
    const __nv_bfloat16* __restrict__ xH, const __nv_bfloat16* __restrict__ xL,
    float* __restrict__ Zf,
    __nv_bfloat16* __restrict__ ZoH, __nv_bfloat16* __restrict__ ZoL,
    __nv_bfloat16* __restrict__ LHo, __nv_bfloat16* __restrict__ LLo,
    float* __restrict__ out) {

    extern __shared__ char smem[];
    const uint32_t sb = smem_u32(smem);
    const int tid = threadIdx.x, lane = tid & 31, wid = tid >> 5;
    const int wg = wid >> 2, w4 = wid & 3;
    const int wm = w4 & 1, wn = w4 >> 1;
    const int b = blockIdx.y, m0 = blockIdx.x * 32;

    auto load_chunk = [&](int k0, int s) {
        const uint32_t st = sb + (uint32_t)s * STG_SZ;
        if (PASS == 1) {
            // fp32 A tile: 32 rows x 256B
            #pragma unroll
            for (int i = 0; i < 2; i++) {
                const int idx = tid + i * 256;
                const int row = idx >> 4, sg = idx & 15;
                cp16(st + (uint32_t)row * 256 + sg * 16,
                     Lf + ((size_t)(b * N_ + m0 + row)) * N_ + k0 + sg * 4);
            }
        } else {
            const int row = tid >> 3, seg = tid & 7;   // 32 rows x 8 segs
            const uint32_t so = (uint32_t)row * 128 + (uint32_t)((seg ^ (row & 7)) << 4);
            const size_t go = ((size_t)(b * N_ + m0 + row)) * N_ + k0 + seg * 8;
            cp16(st + so,        LH + go);
            cp16(st + 4096 + so, LL + go);
        }
        #pragma unroll
        for (int i = 0; i < 2; i++) {
            const int idx = tid + i * 256;
            const int row = idx >> 3, seg = idx & 7;   // 64 rows x 8 segs
            const uint32_t so = (uint32_t)row * 128 + (uint32_t)((seg ^ (row & 7)) << 4);
            cp16(st + 8192 + so,  BHg + (size_t)(b * N_ + k0 + row) * C_ + seg * 8);
            cp16(st + 16384 + so, BLg + (size_t)(b * N_ + k0 + row) * C_ + seg * 8);
        }
        CP_COMMIT();
    };

    float acc[4][4] = {};
    load_chunk(0, 0);
    load_chunk(64, 1);
    load_chunk(128, 2);

    for (int ch = 0; ch < 16; ch++) {
        if (ch < 14)       asm volatile("cp.async.wait_group 2;" ::: "memory");
        else if (ch == 14) asm volatile("cp.async.wait_group 1;" ::: "memory");
        else               asm volatile("cp.async.wait_group 0;" ::: "memory");
        __syncthreads();
        const int s = ch & 3;
        const uint32_t st = sb + (uint32_t)s * STG_SZ;
        char* stp = smem + (size_t)s * STG_SZ;

        if (PASS == 1) {
            // fp32 A chunk -> bf16 hi/lo in-place; persist to global
            const int r = tid >> 3, cs = tid & 7;
            float4 f0 = *(const float4*)(stp + r * 256 + cs * 32);
            float4 f1 = *(const float4*)(stp + r * 256 + cs * 32 + 16);
            __syncthreads();
            uint4 hv, lv;
            split2(f0.x, f0.y, hv.x, lv.x);
            split2(f0.z, f0.w, hv.y, lv.y);
            split2(f1.x, f1.y, hv.z, lv.z);
            split2(f1.z, f1.w, hv.w, lv.w);
            const uint32_t so = (uint32_t)r * 128 + (uint32_t)((cs ^ (r & 7)) << 4);
            *(uint4*)(stp + so) = hv;
            *(uint4*)(stp + 4096 + so) = lv;
            const size_t go = ((size_t)(b * N_ + m0 + r)) * N_ + ch * 64 + cs * 8;
            *(uint4*)(LHo + go) = hv;
            *(uint4*)(LLo + go) = lv;
            __syncthreads();
        }

        mma_block64(st, st + 4096, st + 8192, st + 16384,
                    wm, wn, lane, wg * 2, wg * 2 + 2, acc);

        if (ch + 3 < 16) load_chunk((ch + 3) * 64, (ch + 3) & 3);
    }
    __syncthreads();

    const int crow = wm * 16 + (lane >> 2);
    const int ccol = wn * 32 + 2 * (lane & 3);
    float* ACCp = (float*)(smem + O_ACC);

    // wg1 publishes partial accumulators
    if (wg == 1) {
        #pragma unroll
        for (int j = 0; j < 4; j++)
            #pragma unroll
            for (int h = 0; h < 2; h++) {
                ACCp[(crow + 8 * h) * 64 + ccol + j * 8]     = acc[j][2 * h];
                ACCp[(crow + 8 * h) * 64 + ccol + j * 8 + 1] = acc[j][2 * h + 1];
            }
    }
    __syncthreads();

    if (wg == 0) {
        float zn[4][4];
        #pragma unroll
        for (int j = 0; j < 4; j++)
            #pragma unroll
            for (int h = 0; h < 2; h++) {
                zn[j][2 * h]     = acc[j][2 * h]     + ACCp[(crow + 8 * h) * 64 + ccol + j * 8];
                zn[j][2 * h + 1] = acc[j][2 * h + 1] + ACCp[(crow + 8 * h) * 64 + ccol + j * 8 + 1];
            }
        if (PASS > 1) {
            const float* Sb = Sub + ((size_t)(b * N_ + m0)) * C_;
            #pragma unroll
            for (int j = 0; j < 4; j++) {
                float2 s0 = *(const float2*)(Sb + (size_t)crow * C_ + ccol + j * 8);
                float2 s1 = *(const float2*)(Sb + (size_t)(crow + 8) * C_ + ccol + j * 8);
                zn[j][0] = 2.f * zn[j][0] - s0.x;
                zn[j][1] = 2.f * zn[j][1] - s0.y;
                zn[j][2] = 2.f * zn[j][2] - s1.x;
                zn[j][3] = 2.f * zn[j][3] - s1.y;
            }
        }
        // zn -> smem bf16 hi/lo (SW128 rows)
        #pragma unroll
        for (int j = 0; j < 4; j++) {
            const int seg = wn * 4 + j;
            const int off = (lane & 3) * 4;
            #pragma unroll
            for (int h = 0; h < 2; h++) {
                const int row = crow + h * 8;
                uint32_t hi, lo;
                split2(zn[j][2 * h], zn[j][2 * h + 1], hi, lo);
                const uint32_t so = (uint32_t)row * 128 + (uint32_t)((seg ^ (row & 7)) << 4) + off;
                *(uint32_t*)(smem + O_ZH + so) = hi;
                *(uint32_t*)(smem + O_ZL + so) = lo;
            }
        }
        if (PASS == 1) {
            float* Zb = Zf + ((size_t)(b * N_ + m0)) * C_;
            #pragma unroll
            for (int j = 0; j < 4; j++) {
                *(float2*)(Zb + (size_t)crow * C_ + ccol + j * 8)       = make_float2(zn[j][0], zn[j][1]);
                *(float2*)(Zb + (size_t)(crow + 8) * C_ + ccol + j * 8) = make_float2(zn[j][2], zn[j][3]);
            }
        }
    } else {
        // wg1 stages theta (and x/theta0 for PASS 1)
        const __nv_bfloat16* tHk = thH + PASS * 4096;
        const __nv_bfloat16* tLk = thL + PASS * 4096;
        const int t2 = tid - 128;
        #pragma unroll
        for (int i = 0; i < 4; i++) {
            const int idx = t2 + i * 128;
            const int row = idx >> 3, seg = idx & 7;
            const uint32_t so = (uint32_t)row * 128 + (uint32_t)((seg ^ (row & 7)) << 4);
            *(uint4*)(smem + O_TH + so) = *(const uint4*)(tHk + row * 64 + seg * 8);
            *(uint4*)(smem + O_TL + so) = *(const uint4*)(tLk + row * 64 + seg * 8);
            if (PASS == 1) {
                *(uint4*)(smem + O_T0H + so) = *(const uint4*)(thH + row * 64 + seg * 8);
                *(uint4*)(smem + O_T0L + so) = *(const uint4*)(thL + row * 64 + seg * 8);
            }
        }
        if (PASS == 1) {
            #pragma unroll
            for (int i = 0; i < 2; i++) {
                const int idx = t2 + i * 128;
                const int row = idx >> 3, seg = idx & 7;
                const uint32_t so = (uint32_t)row * 128 + (uint32_t)((seg ^ (row & 7)) << 4);
                *(uint4*)(smem + O_XH + so) = *(const uint4*)(xH + ((size_t)(b * N_ + m0 + row)) * C_ + seg * 8);
                *(uint4*)(smem + O_XL + so) = *(const uint4*)(xL + ((size_t)(b * N_ + m0 + row)) * C_ + seg * 8);
            }
        }
    }
    __syncthreads();

    if (wg == 0) {
        // theta epilogue on tensor cores
        float o[4][4] = {};
        mma_block64(sb + O_ZH, sb + O_ZL, sb + O_TH, sb + O_TL, wm, wn, lane, 0, 4, o);
        if (PASS == 1)
            mma_block64(sb + O_XH, sb + O_XL, sb + O_T0H, sb + O_T0L, wm, wn, lane, 0, 4, o);

        float* ob = out + ((size_t)(b * N_ + m0)) * C_;
        #pragma unroll
        for (int j = 0; j < 4; j++) {
            float2 v0 = make_float2(o[j][0], o[j][1]);
            float2 v1 = make_float2(o[j][2], o[j][3]);
            float* p0 = ob + (size_t)crow * C_ + ccol + j * 8;
            float* p1 = ob + (size_t)(crow + 8) * C_ + ccol + j * 8;
            if (PASS > 1) {
                float2 c0 = *(const float2*)p0, c1 = *(const float2*)p1;
                v0.x += c0.x; v0.y += c0.y; v1.x += c1.x; v1.y += c1.y;
            }
            *(float2*)p0 = v0;
            *(float2*)p1 = v1;
        }
    } else if (PASS < 3) {
        // wg1: zn hi/lo -> global row-major [N][C] (next pass's B operand)
        const int t2 = tid - 128;
        #pragma unroll
        for (int i = 0; i < 2; i++) {
            const int idx = t2 + i * 128;
            const int row = idx >> 3, seg = idx & 7;
            const uint32_t so = (uint32_t)row * 128 + (uint32_t)((seg ^ (row & 7)) << 4);
            *(uint4*)(ZoH + ((size_t)(b * N_ + m0 + row)) * C_ + seg * 8) = *(const uint4*)(smem + O_ZH + so);
            *(uint4*)(ZoL + ((size_t)(b * N_ + m0 + row)) * C_ + seg * 8) = *(const uint4*)(smem + O_ZL + so);
        }
    }
}

extern "C" void kernel_launch(void* const* d_in, const int* in_sizes, int n_in,
                              void* d_out, int out_size) {
    (void)in_sizes; (void)n_in; (void)out_size;
    const float* x  = (const float*)d_in[0];   // [8,1024,64]
    const float* L  = (const float*)d_in[1];   // [8,1024,1024]
    const float* th = (const float*)d_in[2];   // [4,64,64]
    float* out = (float*)d_out;                // [8,1024,64]

    __nv_bfloat16 *lh, *ll, *xh, *xl, *z1h, *z1l, *z2h, *z2l, *thh, *thl;
    float* z1f;
    cudaGetSymbolAddress((void**)&lh, g_LH);
    cudaGetSymbolAddress((void**)&ll, g_LL);
    cudaGetSymbolAddress((void**)&xh, g_xH);
    cudaGetSymbolAddress((void**)&xl, g_xL);
    cudaGetSymbolAddress((void**)&z1h, g_z1H);
    cudaGetSymbolAddress((void**)&z1l, g_z1L);
    cudaGetSymbolAddress((void**)&z2h, g_z2H);
    cudaGetSymbolAddress((void**)&z2l, g_z2L);
    cudaGetSymbolAddress((void**)&thh, g_thH);
    cudaGetSymbolAddress((void**)&thl, g_thL);
    cudaGetSymbolAddress((void**)&z1f, g_Z1f);

    static bool attr_done = false;
    if (!attr_done) {
        cudaFuncSetAttribute(cheb<1>, cudaFuncAttributeMaxDynamicSharedMemorySize, SMEMSZ);
        cudaFuncSetAttribute(cheb<2>, cudaFuncAttributeMaxDynamicSharedMemorySize, SMEMSZ);
        cudaFuncSetAttribute(cheb<3>, cudaFuncAttributeMaxDynamicSharedMemorySize, SMEMSZ);
        attr_done = true;
    }

    // small preps: x and theta hi/lo splits (L split fused into pass 1)
    split_k<<<512, 256>>>((const float4*)x, (uint2*)xh, (uint2*)xl, B_ * N_ * C_ / 4);
    split_k<<<16, 256>>>((const float4*)th, (uint2*)thh, (uint2*)thl, 4 * 64 * 64 / 4);

    dim3 grid(32, 8);
    // pass1: z1 = L x ; out  = x@th0 + z1@th1 ; side: z1f, z1 hi/lo, LH/LL
    cheb<1><<<grid, 256, SMEMSZ>>>(L, nullptr, nullptr, xh, xl, nullptr,
                                   thh, thl, xh, xl, z1f, z1h, z1l, lh, ll, out);
    // pass2: z2 = 2 L z1 - x ; out += z2@th2 ; side: z2 hi/lo
    cheb<2><<<grid, 256, SMEMSZ>>>(nullptr, lh, ll, z1h, z1l, x,
                                   thh, thl, xh, xl, nullptr, z2h, z2l, nullptr, nullptr, out);
    // pass3: z3 = 2 L z2 - z1 ; out += z3@th3
    cheb<3><<<grid, 256, SMEMSZ>>>(nullptr, lh, ll, z2h, z2l, z1f,
                                   thh, thl, xh, xl, nullptr, nullptr, nullptr, nullptr, nullptr, out);
}